// round 16
// speedup vs baseline: 3.0113x; 1.0591x over previous
#include <cuda_runtime.h>
#include <cuda_bf16.h>
#include <stdint.h>
#include <math.h>

// Problem constants
#define B 8
#define L 1024
#define E 1024
#define H 16
#define D 64
#define NTOK (B * L)          // 8192
#define QKVW (3 * E)          // 3072
#define QSCALE (0.125f * 1.4426950408889634f)  // fold log2(e): exp -> exp2
#define EPS 1e-5f

// ---------------- scratch (device globals; no allocation allowed) ----------
__device__ float g_h[NTOK * E];
__device__ float g_rowsum[B * H * L];
__device__ float g_colsum[B * L];
__device__ __nv_bfloat16 g_xh[NTOK * E];
__device__ __nv_bfloat16 g_xl[NTOK * E];
__device__ __nv_bfloat16 g_wqh[QKVW * E];
__device__ __nv_bfloat16 g_wql[QKVW * E];
__device__ __nv_bfloat16 g_ch[NTOK * E];
__device__ __nv_bfloat16 g_cl[NTOK * E];
__device__ __nv_bfloat16 g_woh[E * E];
__device__ __nv_bfloat16 g_wol[E * E];
__device__ __nv_bfloat16 g_qhh[B * H * L * D];  // [bh][l][d], pre-scaled (log2 domain)
__device__ __nv_bfloat16 g_qll[B * H * L * D];
__device__ __nv_bfloat16 g_khh[B * H * L * D];  // [bh][l][d] (hi only)
__device__ __nv_bfloat16 g_vhh[B * H * D * L];  // [bh][d][l]
__device__ __nv_bfloat16 g_vll[B * H * D * L];

// ================= base-ISA PTX helpers =====================================
__device__ __forceinline__ uint32_t smem_u32(const void* p) {
    uint32_t a;
    asm("{ .reg .u64 t; cvta.to.shared.u64 t, %1; cvt.u32.u64 %0, t; }"
        : "=r"(a) : "l"(p));
    return a;
}
__device__ __forceinline__ void ldsm_x4(uint32_t addr, uint32_t& r0, uint32_t& r1,
                                        uint32_t& r2, uint32_t& r3) {
    asm volatile("ldmatrix.sync.aligned.m8n8.x4.shared.b16 {%0,%1,%2,%3}, [%4];"
                 : "=r"(r0), "=r"(r1), "=r"(r2), "=r"(r3) : "r"(addr));
}
__device__ __forceinline__ void mma16816(float* c,
                                         uint32_t a0, uint32_t a1, uint32_t a2, uint32_t a3,
                                         uint32_t b0, uint32_t b1) {
    asm volatile(
        "mma.sync.aligned.m16n8k16.row.col.f32.bf16.bf16.f32 "
        "{%0,%1,%2,%3}, {%4,%5,%6,%7}, {%8,%9}, {%0,%1,%2,%3};"
        : "+f"(c[0]), "+f"(c[1]), "+f"(c[2]), "+f"(c[3])
        : "r"(a0), "r"(a1), "r"(a2), "r"(a3), "r"(b0), "r"(b1));
}
__device__ __forceinline__ void cp16(uint32_t sdst, const void* gsrc) {
    asm volatile("cp.async.cg.shared.global [%0], [%1], 16;"
                 :: "r"(sdst), "l"(gsrc) : "memory");
}

// 2^x via MUFU (ex2.approx, ~2 ulp): 1 instruction -> relieves issue pressure
__device__ __forceinline__ float fexp2(float t) {
    float r;
    asm("ex2.approx.f32 %0, %1;" : "=f"(r) : "f"(t));
    return r;
}

__device__ __forceinline__ void splitpack(float x, float y, uint32_t& h2, uint32_t& l2) {
    __nv_bfloat16 hx = __float2bfloat16_rn(x), hy = __float2bfloat16_rn(y);
    __nv_bfloat162 hh = __halves2bfloat162(hx, hy);
    __nv_bfloat162 ll = __halves2bfloat162(
        __float2bfloat16_rn(x - __bfloat162float(hx)),
        __float2bfloat16_rn(y - __bfloat162float(hy)));
    h2 = *(uint32_t*)&hh;
    l2 = *(uint32_t*)&ll;
}

// ============ GEMM mainloop (shared): 128x128 CTA, K=32 chunks, 3 stages ===
#define GM_STAGE 32768u
#define SMEM_GEMM_BYTES (1024 + 3 * 32768)

#define GEMM_MAINLOOP()                                                        \
    float acc[2][8][4];                                                        \
    _Pragma("unroll")                                                          \
    for (int i = 0; i < 2; i++)                                                \
        _Pragma("unroll")                                                      \
        for (int j = 0; j < 8; j++)                                            \
            _Pragma("unroll")                                                  \
            for (int k = 0; k < 4; k++) acc[i][j][k] = 0.f;                    \
    const int NCHUNK = 32;                                                     \
    ISSUE_CHUNK(0, 0);                                                         \
    ISSUE_CHUNK(1, 1);                                                         \
    int buf = 0;                                                               \
    for (int c = 0; c < NCHUNK; c++) {                                         \
        if (c < NCHUNK - 1)                                                    \
            asm volatile("cp.async.wait_group 1;" ::: "memory");               \
        else                                                                   \
            asm volatile("cp.async.wait_group 0;" ::: "memory");               \
        __syncthreads();                                                       \
        if (c + 2 < NCHUNK) {                                                  \
            const int nbuf = (buf + 2 >= 3) ? buf - 1 : buf + 2;               \
            ISSUE_CHUNK(c + 2, nbuf);                                          \
        }                                                                      \
        const uint32_t Ab = s0 + (uint32_t)buf * GM_STAGE;                     \
        const uint32_t Wb = Ab + 16384u;                                       \
        _Pragma("unroll")                                                      \
        for (int ks = 0; ks < 2; ks++) {                                       \
            uint32_t aH[2][4], aL[2][4];                                       \
            _Pragma("unroll")                                                  \
            for (int mi = 0; mi < 2; mi++) {                                   \
                const int r = wm + mi * 16 + (lane & 15);                      \
                const int chunk = ks * 2 + (lane >> 4);                        \
                const uint32_t ad = Ab + (uint32_t)(r * 128)                   \
                                  + (uint32_t)(((chunk ^ (r & 7)) * 16));      \
                const uint32_t al = Ab + (uint32_t)(r * 128)                   \
                                  + (uint32_t)((((chunk + 4) ^ (r & 7)) * 16));\
                ldsm_x4(ad, aH[mi][0], aH[mi][1], aH[mi][2], aH[mi][3]);       \
                ldsm_x4(al, aL[mi][0], aL[mi][1], aL[mi][2], aL[mi][3]);       \
            }                                                                  \
            _Pragma("unroll")                                                  \
            for (int nj = 0; nj < 4; nj++) {                                   \
                const int nr = wn + nj * 16 + ((lane >> 4) & 1) * 8 + (lane & 7);\
                const int ch = ks * 2 + ((lane >> 3) & 1);                     \
                const uint32_t wd = Wb + (uint32_t)(nr * 128)                  \
                                  + (uint32_t)(((ch ^ (nr & 7)) * 16));        \
                const uint32_t wl = Wb + (uint32_t)(nr * 128)                  \
                                  + (uint32_t)((((ch + 4) ^ (nr & 7)) * 16));  \
                uint32_t w0, w1, w2, w3, v0, v1, v2, v3;                       \
                ldsm_x4(wd, w0, w1, w2, w3);                                   \
                ldsm_x4(wl, v0, v1, v2, v3);                                   \
                _Pragma("unroll")                                              \
                for (int mi = 0; mi < 2; mi++) {                               \
                    float* c0 = acc[mi][nj * 2 + 0];                           \
                    float* c1 = acc[mi][nj * 2 + 1];                           \
                    mma16816(c0, aH[mi][0], aH[mi][1], aH[mi][2], aH[mi][3], w0, w1);\
                    mma16816(c1, aH[mi][0], aH[mi][1], aH[mi][2], aH[mi][3], w2, w3);\
                    mma16816(c0, aH[mi][0], aH[mi][1], aH[mi][2], aH[mi][3], v0, v1);\
                    mma16816(c1, aH[mi][0], aH[mi][1], aH[mi][2], aH[mi][3], v2, v3);\
                    mma16816(c0, aL[mi][0], aL[mi][1], aL[mi][2], aL[mi][3], w0, w1);\
                    mma16816(c1, aL[mi][0], aL[mi][1], aL[mi][2], aL[mi][3], w2, w3);\
                }                                                              \
            }                                                                  \
        }                                                                      \
        buf = (buf + 1 >= 3) ? 0 : buf + 1;                                    \
    }

#define ISSUE_CHUNK(c, buf) do {                                              \
    const int k0_ = (c) * 32;                                                 \
    const char* gah_ = (const char*)(Ah + growA + k0_);                       \
    const char* gal_ = (const char*)(Al + growA + k0_);                       \
    const char* gwh_ = (const char*)(Wh + growW + k0_);                       \
    const char* gwl_ = (const char*)(Wl + growW + k0_);                       \
    const uint32_t st_ = s0 + (uint32_t)(buf) * GM_STAGE;                     \
    const uint32_t da_ = st_ + (uint32_t)lrow * 128u;                         \
    const uint32_t dw_ = st_ + 16384u + (uint32_t)lrow * 128u;                \
    _Pragma("unroll")                                                         \
    for (int i = 0; i < 2; i++) {                                             \
        const int cc = lhalf * 2 + i;                                         \
        const uint32_t swh = (uint32_t)((cc ^ rsw) * 16);                     \
        const uint32_t swl = (uint32_t)(((cc + 4) ^ rsw) * 16);               \
        cp16(da_ + swh, gah_ + i * 16);                                       \
        cp16(da_ + swl, gal_ + i * 16);                                       \
        cp16(dw_ + swh, gwh_ + i * 16);                                       \
        cp16(dw_ + swl, gwl_ + i * 16);                                       \
    }                                                                         \
    asm volatile("cp.async.commit_group;" ::: "memory");                      \
} while (0)

// ---- GEMM 2: h = x + ctx @ w_out^T + b_out (fp32 out) ---------------------
__global__ __launch_bounds__(256, 2) void gemm_mma_res(
    const __nv_bfloat16* __restrict__ Ah, const __nv_bfloat16* __restrict__ Al,
    const __nv_bfloat16* __restrict__ Wh, const __nv_bfloat16* __restrict__ Wl,
    const float* __restrict__ bias, const float* __restrict__ Res,
    float* __restrict__ C, int N)
{
    extern __shared__ char smraw[];
    const uint32_t sb = smem_u32(smraw);
    const uint32_t s0 = (sb + 1023) & ~1023u;

    const int tid = threadIdx.x;
    const int lane = tid & 31;
    const int wid = tid >> 5;
    const int bm = blockIdx.y * 128;
    const int bn = blockIdx.x * 128;
    const int wm = ((wid >> 1) & 3) * 32;
    const int wn = (wid & 1) * 64;

    const int lrow = tid >> 1;
    const int lhalf = tid & 1;
    const size_t growA = (size_t)(bm + lrow) * E + lhalf * 16;
    const size_t growW = (size_t)(bn + lrow) * E + lhalf * 16;
    const int rsw = lrow & 7;

    GEMM_MAINLOOP()

    const int gid = lane >> 2, qid = lane & 3;
#pragma unroll
    for (int mi = 0; mi < 2; mi++) {
        const int r = bm + wm + mi * 16 + gid;
#pragma unroll
        for (int nj = 0; nj < 8; nj++) {
            const int col = bn + wn + nj * 8 + qid * 2;
            const float2 bv = *(const float2*)(bias + col);
            const float2 r0 = *(const float2*)(Res + (size_t)r * N + col);
            const float2 r1 = *(const float2*)(Res + (size_t)(r + 8) * N + col);
            float2 o0 = {acc[mi][nj][0] + bv.x + r0.x, acc[mi][nj][1] + bv.y + r0.y};
            float2 o1 = {acc[mi][nj][2] + bv.x + r1.x, acc[mi][nj][3] + bv.y + r1.y};
            *(float2*)(C + (size_t)r * N + col) = o0;
            *(float2*)(C + (size_t)(r + 8) * N + col) = o1;
        }
    }
}

// ---- GEMM 1: qkv projection, fused epilogue -> per-head bf16 splits -------
__global__ __launch_bounds__(256, 2) void gemm_qkv(
    const __nv_bfloat16* __restrict__ Ah, const __nv_bfloat16* __restrict__ Al,
    const __nv_bfloat16* __restrict__ Wh, const __nv_bfloat16* __restrict__ Wl,
    const float* __restrict__ bias,
    __nv_bfloat16* __restrict__ qh, __nv_bfloat16* __restrict__ ql,
    __nv_bfloat16* __restrict__ kh,
    __nv_bfloat16* __restrict__ vh, __nv_bfloat16* __restrict__ vl)
{
    extern __shared__ char smraw[];
    const uint32_t sb = smem_u32(smraw);
    const uint32_t s0 = (sb + 1023) & ~1023u;

    const int tid = threadIdx.x;
    const int lane = tid & 31;
    const int wid = tid >> 5;
    const int bm = blockIdx.y * 128;
    const int bn = blockIdx.x * 128;
    const int wm = ((wid >> 1) & 3) * 32;
    const int wn = (wid & 1) * 64;

    const int lrow = tid >> 1;
    const int lhalf = tid & 1;
    const size_t growA = (size_t)(bm + lrow) * E + lhalf * 16;
    const size_t growW = (size_t)(bn + lrow) * E + lhalf * 16;
    const int rsw = lrow & 7;

    GEMM_MAINLOOP()

    __syncthreads();

    const int gid = lane >> 2, qid = lane & 3;
    const int btok = bm >> 10;
    const int l0 = bm & 1023;

    if (bn < 2 * E) {
        const bool isQ = (bn < E);
        const float sc = isQ ? QSCALE : 1.f;
        const int colbase = isQ ? bn : bn - E;
#pragma unroll
        for (int mi = 0; mi < 2; mi++) {
            const int tok = l0 + wm + mi * 16 + gid;
#pragma unroll
            for (int nj = 0; nj < 8; nj++) {
                const int col = colbase + wn + nj * 8 + qid * 2;
                const int head = col >> 6;
                const int d = col & 63;
                const float2 bv = *(const float2*)(bias + (bn + wn + nj * 8 + qid * 2));
                const float v0 = (acc[mi][nj][0] + bv.x) * sc;
                const float v1 = (acc[mi][nj][1] + bv.y) * sc;
                const float v2 = (acc[mi][nj][2] + bv.x) * sc;
                const float v3 = (acc[mi][nj][3] + bv.y) * sc;
                const size_t base = (((size_t)(btok * H + head)) * L + tok) * 64 + d;
                uint32_t h2, l2;
                if (isQ) {
                    splitpack(v0, v1, h2, l2);
                    *(uint32_t*)(qh + base) = h2;
                    *(uint32_t*)(ql + base) = l2;
                    splitpack(v2, v3, h2, l2);
                    *(uint32_t*)(qh + base + 8 * 64) = h2;
                    *(uint32_t*)(ql + base + 8 * 64) = l2;
                } else {
                    __nv_bfloat162 p0 = __halves2bfloat162(
                        __float2bfloat16_rn(v0), __float2bfloat16_rn(v1));
                    __nv_bfloat162 p1 = __halves2bfloat162(
                        __float2bfloat16_rn(v2), __float2bfloat16_rn(v3));
                    *(uint32_t*)(kh + base) = *(uint32_t*)&p0;
                    *(uint32_t*)(kh + base + 8 * 64) = *(uint32_t*)&p1;
                }
            }
        }
    } else {
        float* vt = (float*)(smraw + (s0 - sb));   // 128 x 65 fp32
        const int colbase = bn - 2 * E;
#pragma unroll
        for (int half = 0; half < 2; half++) {
            if ((wid & 1) == half) {
#pragma unroll
                for (int mi = 0; mi < 2; mi++) {
                    const int rl = wm + mi * 16 + gid;
#pragma unroll
                    for (int nj = 0; nj < 8; nj++) {
                        const int cl = nj * 8 + qid * 2;
                        const float2 bv = *(const float2*)(
                            bias + 2 * E + colbase + half * 64 + cl);
                        vt[rl * 65 + cl] = acc[mi][nj][0] + bv.x;
                        vt[rl * 65 + cl + 1] = acc[mi][nj][1] + bv.y;
                        vt[(rl + 8) * 65 + cl] = acc[mi][nj][2] + bv.x;
                        vt[(rl + 8) * 65 + cl + 1] = acc[mi][nj][3] + bv.y;
                    }
                }
            }
            __syncthreads();
            {
                const int d = tid >> 2;
                const int t0 = (tid & 3) * 32;
                const int head = (colbase >> 6) + half;
                const size_t vb = ((size_t)(btok * H + head) * D + d) * L + l0 + t0;
                uint32_t hb[16], lb[16];
#pragma unroll
                for (int i = 0; i < 16; i++)
                    splitpack(vt[(t0 + 2 * i) * 65 + d],
                              vt[(t0 + 2 * i + 1) * 65 + d], hb[i], lb[i]);
#pragma unroll
                for (int u = 0; u < 4; u++) {
                    *(uint4*)(vh + vb + u * 8) = *(uint4*)&hb[u * 4];
                    *(uint4*)(vl + vb + u * 8) = *(uint4*)&lb[u * 4];
                }
            }
            __syncthreads();
        }
    }
}
#undef ISSUE_CHUNK
#undef GEMM_MAINLOOP

// ---------------- merged exact fp32 -> bf16 hi/lo splits (x, w_qkv, w_out) --
#define N4_X   (NTOK * E / 4)
#define N4_WQ  (QKVW * E / 4)
#define N4_WO  (E * E / 4)
__global__ __launch_bounds__(256) void split_all(
    const float4* __restrict__ x, __nv_bfloat162* __restrict__ xh,
    __nv_bfloat162* __restrict__ xl,
    const float4* __restrict__ wq, __nv_bfloat162* __restrict__ wqh,
    __nv_bfloat162* __restrict__ wql,
    const float4* __restrict__ wo, __nv_bfloat162* __restrict__ woh,
    __nv_bfloat162* __restrict__ wol)
{
    int i = blockIdx.x * blockDim.x + threadIdx.x;
    const float4* src;
    __nv_bfloat162 *hi, *lo;
    int j;
    if (i < N4_X) { src = x; hi = xh; lo = xl; j = i; }
    else if (i < N4_X + N4_WQ) { src = wq; hi = wqh; lo = wql; j = i - N4_X; }
    else if (i < N4_X + N4_WQ + N4_WO) { src = wo; hi = woh; lo = wol; j = i - N4_X - N4_WQ; }
    else return;
    float4 v = src[j];
    uint32_t h0, l0, h1, l1;
    splitpack(v.x, v.y, h0, l0);
    splitpack(v.z, v.w, h1, l1);
    ((uint32_t*)hi)[j * 2 + 0] = h0;
    ((uint32_t*)hi)[j * 2 + 1] = h1;
    ((uint32_t*)lo)[j * 2 + 0] = l0;
    ((uint32_t*)lo)[j * 2 + 1] = l1;
}

// ======================= attention (m=0 softmax, single-pass ctx) ===========
// 64-row K hi-only tile loader: 64 rows x 128B
#define LOAD_KH(kt, buf, STG, OFF)                                            \
    do {                                                                      \
        const int r_ = tid >> 2;                                              \
        const int q_ = tid & 3;                                               \
        const __nv_bfloat16* gh_ = kh + ((size_t)bh * L + (kt) * 64 + r_) * 64 + q_ * 16; \
        const uint32_t sh_ = s0 + (uint32_t)(buf) * (STG) + (OFF) + (uint32_t)(r_ * 128); \
        _Pragma("unroll")                                                     \
        for (int i = 0; i < 2; i++) {                                         \
            const int cc = q_ * 2 + i;                                        \
            const uint32_t sw = (uint32_t)((cc ^ (r_ & 7)) * 16);             \
            cp16(sh_ + sw, gh_ + i * 8);                                      \
        }                                                                     \
    } while (0)

// ---- attn_main: unnormalized ctx + rowsum in ONE pass ----------------------
// stage 24KB: K-hi 8K | V-hi 8K | V-lo 8K. 3 stages.
#define PB_STAGE 24576u
#define SMEM_MAIN (1024 + 3 * 24576)
__global__ __launch_bounds__(256, 2) void attn_main(
    const __nv_bfloat16* __restrict__ qh, const __nv_bfloat16* __restrict__ ql,
    const __nv_bfloat16* __restrict__ kh,
    const __nv_bfloat16* __restrict__ vh, const __nv_bfloat16* __restrict__ vl,
    float* __restrict__ rowsum,
    __nv_bfloat16* __restrict__ ch, __nv_bfloat16* __restrict__ cl)
{
    extern __shared__ char smraw[];
    const uint32_t sb = smem_u32(smraw);
    const uint32_t s0 = (sb + 1023) & ~1023u;

    const int tid = threadIdx.x;
    const int lane = tid & 31;
    const int wid = tid >> 5;
    const int gid = lane >> 2, qid = lane & 3;
    const int bh = blockIdx.z * H + blockIdx.y;
    const int qrow0 = blockIdx.x * 128 + wid * 16;

    uint32_t aH[4][4], aL[4][4];
    {
        const size_t qb = (size_t)bh * L + qrow0;
#pragma unroll
        for (int ks = 0; ks < 4; ks++)
#pragma unroll
            for (int r = 0; r < 4; r++) {
                const int row = gid + (r & 1) * 8;
                const int col = ks * 16 + (r >> 1) * 8 + qid * 2;
                aH[ks][r] = *(const uint32_t*)(qh + (qb + row) * 64 + col);
                aL[ks][r] = *(const uint32_t*)(ql + (qb + row) * 64 + col);
            }
    }

    float lsum0 = 0.f, lsum1 = 0.f;
    float o[8][4];
#pragma unroll
    for (int j = 0; j < 8; j++)
#pragma unroll
        for (int k = 0; k < 4; k++) o[j][k] = 0.f;

#define LOAD_V(kt, buf)                                                       \
    do {                                                                      \
        const int r_ = tid >> 2;                                              \
        const int q_ = tid & 3;                                               \
        const __nv_bfloat16* gh_ = vh + ((size_t)bh * D + r_) * L + (kt) * 64 + q_ * 16; \
        const __nv_bfloat16* gl_ = vl + ((size_t)bh * D + r_) * L + (kt) * 64 + q_ * 16; \
        const uint32_t sv_ = s0 + (uint32_t)(buf) * PB_STAGE + 8192u          \
                           + (uint32_t)(r_ * 128);                            \
        _Pragma("unroll")                                                     \
        for (int i = 0; i < 2; i++) {                                         \
            const int cc = q_ * 2 + i;                                        \
            const uint32_t sw = (uint32_t)((cc ^ (r_ & 7)) * 16);             \
            cp16(sv_ + sw, gh_ + i * 8);                                      \
            cp16(sv_ + 8192u + sw, gl_ + i * 8);                              \
        }                                                                     \
    } while (0)

    LOAD_KH(0, 0, PB_STAGE, 0u);
    LOAD_V(0, 0);
    asm volatile("cp.async.commit_group;" ::: "memory");
    LOAD_KH(1, 1, PB_STAGE, 0u);
    LOAD_V(1, 1);
    asm volatile("cp.async.commit_group;" ::: "memory");

    int buf = 0;
    for (int kt = 0; kt < 16; kt++) {
        if (kt < 15)
            asm volatile("cp.async.wait_group 1;" ::: "memory");
        else
            asm volatile("cp.async.wait_group 0;" ::: "memory");
        __syncthreads();

        if (kt + 2 < 16) {
            const int nbuf = (buf + 2 >= 3) ? buf - 1 : buf + 2;
            LOAD_KH(kt + 2, nbuf, PB_STAGE, 0u);
            LOAD_V(kt + 2, nbuf);
            asm volatile("cp.async.commit_group;" ::: "memory");
        }

        float s[8][4];
#pragma unroll
        for (int t = 0; t < 8; t++)
#pragma unroll
            for (int j = 0; j < 4; j++) s[t][j] = 0.f;

        // 2-term QK: (qh + ql) x kh
        const uint32_t Kb = s0 + (uint32_t)buf * PB_STAGE;
#pragma unroll
        for (int ks = 0; ks < 4; ks++) {
#pragma unroll
            for (int nj = 0; nj < 4; nj++) {
                const int nr = nj * 16 + ((lane >> 4) & 1) * 8 + (lane & 7);
                const int ch_ = ks * 2 + ((lane >> 3) & 1);
                const uint32_t ad = Kb + (uint32_t)(nr * 128)
                                  + (uint32_t)((ch_ ^ (nr & 7)) * 16);
                uint32_t b0, b1, b2, b3;
                ldsm_x4(ad, b0, b1, b2, b3);
                mma16816(s[nj * 2 + 0], aH[ks][0], aH[ks][1], aH[ks][2],
                         aH[ks][3], b0, b1);
                mma16816(s[nj * 2 + 1], aH[ks][0], aH[ks][1], aH[ks][2],
                         aH[ks][3], b2, b3);
                mma16816(s[nj * 2 + 0], aL[ks][0], aL[ks][1], aL[ks][2],
                         aL[ks][3], b0, b1);
                mma16816(s[nj * 2 + 1], aL[ks][0], aL[ks][1], aL[ks][2],
                         aL[ks][3], b2, b3);
            }
        }

        // unnormalized e = 2^s; accumulate rowsum
#pragma unroll
        for (int t = 0; t < 8; t++) {
            s[t][0] = fexp2(s[t][0]);
            s[t][1] = fexp2(s[t][1]);
            s[t][2] = fexp2(s[t][2]);
            s[t][3] = fexp2(s[t][3]);
            lsum0 += s[t][0] + s[t][1];
            lsum1 += s[t][2] + s[t][3];
        }

        // PV: (eH + eL) x vh + eH x vl  (unnormalized accumulation)
        const uint32_t Vb = s0 + (uint32_t)buf * PB_STAGE + 8192u;
#pragma unroll
        for (int kk = 0; kk < 4; kk++) {
            uint32_t pH[4], pL[4];
            splitpack(s[2 * kk][0], s[2 * kk][1], pH[0], pL[0]);
            splitpack(s[2 * kk][2], s[2 * kk][3], pH[1], pL[1]);
            splitpack(s[2 * kk + 1][0], s[2 * kk + 1][1], pH[2], pL[2]);
            splitpack(s[2 * kk + 1][2], s[2 * kk + 1][3], pH[3], pL[3]);
#pragma unroll
            for (int nj = 0; nj < 4; nj++) {
                const int nr = nj * 16 + ((lane >> 4) & 1) * 8 + (lane & 7);
                const int ch_ = kk * 2 + ((lane >> 3) & 1);
                const uint32_t ad = Vb + (uint32_t)(nr * 128)
                                  + (uint32_t)((ch_ ^ (nr & 7)) * 16);
                uint32_t b0, b1, b2, b3, c0, c1, c2, c3;
                ldsm_x4(ad, b0, b1, b2, b3);
                ldsm_x4(ad + 8192u, c0, c1, c2, c3);
                float* o0 = o[nj * 2 + 0];
                float* o1 = o[nj * 2 + 1];
                mma16816(o0, pH[0], pH[1], pH[2], pH[3], b0, b1);
                mma16816(o1, pH[0], pH[1], pH[2], pH[3], b2, b3);
                mma16816(o0, pH[0], pH[1], pH[2], pH[3], c0, c1);
                mma16816(o1, pH[0], pH[1], pH[2], pH[3], c2, c3);
                mma16816(o0, pL[0], pL[1], pL[2], pL[3], b0, b1);
                mma16816(o1, pL[0], pL[1], pL[2], pL[3], b2, b3);
            }
        }

        buf = (buf + 1 >= 3) ? 0 : buf + 1;
    }

    // finalize rowsum across qid lanes, write, normalize o
    lsum0 += __shfl_xor_sync(0xffffffffu, lsum0, 1);
    lsum0 += __shfl_xor_sync(0xffffffffu, lsum0, 2);
    lsum1 += __shfl_xor_sync(0xffffffffu, lsum1, 1);
    lsum1 += __shfl_xor_sync(0xffffffffu, lsum1, 2);
    const int ridx = bh * L + qrow0 + gid;
    if (qid == 0) {
        rowsum[ridx] = lsum0;
        rowsum[ridx + 8] = lsum1;
    }
    const float il0 = 1.f / lsum0, il1 = 1.f / lsum1;

    const int b = blockIdx.z, h = blockIdx.y;
    const size_t tok0 = (size_t)b * L + qrow0;
#pragma unroll
    for (int j = 0; j < 8; j++) {
        const int dcol = h * 64 + j * 8 + qid * 2;
        uint32_t h2, l2;
        splitpack(o[j][0] * il0, o[j][1] * il0, h2, l2);
        *(uint32_t*)(ch + (tok0 + gid) * E + dcol) = h2;
        *(uint32_t*)(cl + (tok0 + gid) * E + dcol) = l2;
        splitpack(o[j][2] * il1, o[j][3] * il1, h2, l2);
        *(uint32_t*)(ch + (tok0 + gid + 8) * E + dcol) = h2;
        *(uint32_t*)(cl + (tok0 + gid + 8) * E + dcol) = l2;
    }
}
#undef LOAD_V

// ---- attn_colsum: avg_attn column sums (1-term QK, uses rowsum) ------------
#define SMEM_COLS (1024 + 3 * 8192 + 4096)
__global__ __launch_bounds__(256, 3) void attn_colsum(
    const __nv_bfloat16* __restrict__ qh,
    const __nv_bfloat16* __restrict__ kh,
    const float* __restrict__ rowsum,
    float* __restrict__ colsum)
{
    extern __shared__ char smraw[];
    const uint32_t sb = smem_u32(smraw);
    const uint32_t s0 = (sb + 1023) & ~1023u;
    float* colAll = (float*)(smraw + (s0 - sb) + 3 * 8192);

    const int tid = threadIdx.x;
    const int lane = tid & 31;
    const int wid = tid >> 5;
    const int gid = lane >> 2, qid = lane & 3;
    const int bh = blockIdx.z * H + blockIdx.y;
    const int qrow0 = blockIdx.x * 128 + wid * 16;

#pragma unroll
    for (int i = 0; i < 4; i++) colAll[tid * 4 + i] = 0.f;

    uint32_t aH[4][4];
    {
        const size_t qb = (size_t)bh * L + qrow0;
#pragma unroll
        for (int ks = 0; ks < 4; ks++)
#pragma unroll
            for (int r = 0; r < 4; r++) {
                const int row = gid + (r & 1) * 8;
                const int col = ks * 16 + (r >> 1) * 8 + qid * 2;
                aH[ks][r] = *(const uint32_t*)(qh + (qb + row) * 64 + col);
            }
    }

    const int ridx = bh * L + qrow0 + gid;
    const float il0 = 1.f / rowsum[ridx], il1 = 1.f / rowsum[ridx + 8];

    LOAD_KH(0, 0, 8192u, 0u);
    asm volatile("cp.async.commit_group;" ::: "memory");
    LOAD_KH(1, 1, 8192u, 0u);
    asm volatile("cp.async.commit_group;" ::: "memory");

    int buf = 0;
    for (int kt = 0; kt < 16; kt++) {
        if (kt < 15)
            asm volatile("cp.async.wait_group 1;" ::: "memory");
        else
            asm volatile("cp.async.wait_group 0;" ::: "memory");
        __syncthreads();

        if (kt + 2 < 16) {
            const int nbuf = (buf + 2 >= 3) ? buf - 1 : buf + 2;
            LOAD_KH(kt + 2, nbuf, 8192u, 0u);
            asm volatile("cp.async.commit_group;" ::: "memory");
        }

        float s[8][4];
#pragma unroll
        for (int t = 0; t < 8; t++)
#pragma unroll
            for (int j = 0; j < 4; j++) s[t][j] = 0.f;

        const uint32_t Kb = s0 + (uint32_t)buf * 8192u;
#pragma unroll
        for (int ks = 0; ks < 4; ks++) {
#pragma unroll
            for (int nj = 0; nj < 4; nj++) {
                const int nr = nj * 16 + ((lane >> 4) & 1) * 8 + (lane & 7);
                const int ch = ks * 2 + ((lane >> 3) & 1);
                const uint32_t ad = Kb + (uint32_t)(nr * 128)
                                  + (uint32_t)((ch ^ (nr & 7)) * 16);
                uint32_t b0, b1, b2, b3;
                ldsm_x4(ad, b0, b1, b2, b3);
                mma16816(s[nj * 2 + 0], aH[ks][0], aH[ks][1], aH[ks][2],
                         aH[ks][3], b0, b1);
                mma16816(s[nj * 2 + 1], aH[ks][0], aH[ks][1], aH[ks][2],
                         aH[ks][3], b2, b3);
            }
        }

#pragma unroll
        for (int t = 0; t < 8; t++) {
            float v0 = fexp2(s[t][0]) * il0 + fexp2(s[t][2]) * il1;
            float v1 = fexp2(s[t][1]) * il0 + fexp2(s[t][3]) * il1;
            v0 += __shfl_xor_sync(0xffffffffu, v0, 4);
            v0 += __shfl_xor_sync(0xffffffffu, v0, 8);
            v0 += __shfl_xor_sync(0xffffffffu, v0, 16);
            v1 += __shfl_xor_sync(0xffffffffu, v1, 4);
            v1 += __shfl_xor_sync(0xffffffffu, v1, 8);
            v1 += __shfl_xor_sync(0xffffffffu, v1, 16);
            if (gid == 0) {
                const int col = kt * 64 + t * 8 + qid * 2;
                atomicAdd(&colAll[col], v0);
                atomicAdd(&colAll[col + 1], v1);
            }
        }

        buf = (buf + 1 >= 3) ? 0 : buf + 1;
    }

    __syncthreads();
    const int b = blockIdx.z;
#pragma unroll
    for (int i = 0; i < 4; i++)
        atomicAdd(&colsum[b * L + tid * 4 + i], colAll[tid * 4 + i]);
}
#undef LOAD_KH

// ---------------- zero init -------------------------------------------------
__global__ void zero_kernel(float* __restrict__ out, float* __restrict__ colsum) {
    int i = blockIdx.x * blockDim.x + threadIdx.x;
    if (i < B * E) { out[i] = 0.f; colsum[i] = 0.f; }
}

// ---------------- fused LayerNorm + pool ------------------------------------
__global__ __launch_bounds__(256) void ln_pool(
    const float* __restrict__ hbuf, float* __restrict__ out)
{
    __shared__ float accs[1024];
    const int tid = threadIdx.x;
    const int lane = tid & 31, wid = tid >> 5;
    const int b = blockIdx.y;
    const int l0 = blockIdx.x * 64;

#pragma unroll
    for (int i = 0; i < 4; i++) accs[tid * 4 + i] = 0.f;
    __syncthreads();

    float a[8][4];
#pragma unroll
    for (int i = 0; i < 8; i++)
#pragma unroll
        for (int j = 0; j < 4; j++) a[i][j] = 0.f;

    for (int r = 0; r < 8; r++) {
        const size_t row = (size_t)(b * L + l0 + wid * 8 + r);
        float4 v[8];
        float s = 0.f, s2 = 0.f;
#pragma unroll
        for (int i = 0; i < 8; i++) {
            v[i] = *(const float4*)(hbuf + row * E + i * 128 + lane * 4);
            s += v[i].x + v[i].y + v[i].z + v[i].w;
            s2 += v[i].x * v[i].x + v[i].y * v[i].y + v[i].z * v[i].z + v[i].w * v[i].w;
        }
#pragma unroll
        for (int off = 16; off >= 1; off >>= 1) {
            s += __shfl_xor_sync(0xffffffffu, s, off);
            s2 += __shfl_xor_sync(0xffffffffu, s2, off);
        }
        const float mu = s * (1.f / E);
        const float rstd = rsqrtf(s2 * (1.f / E) - mu * mu + EPS);
        const float nm = mu * rstd;
#pragma unroll
        for (int i = 0; i < 8; i++) {
            a[i][0] = fmaf(v[i].x, rstd, a[i][0] - nm);
            a[i][1] = fmaf(v[i].y, rstd, a[i][1] - nm);
            a[i][2] = fmaf(v[i].z, rstd, a[i][2] - nm);
            a[i][3] = fmaf(v[i].w, rstd, a[i][3] - nm);
        }
    }

#pragma unroll
    for (int i = 0; i < 8; i++) {
        const int e = i * 128 + lane * 4;
        atomicAdd(&accs[e + 0], a[i][0]);
        atomicAdd(&accs[e + 1], a[i][1]);
        atomicAdd(&accs[e + 2], a[i][2]);
        atomicAdd(&accs[e + 3], a[i][3]);
    }
    __syncthreads();
#pragma unroll
    for (int i = 0; i < 4; i++)
        atomicAdd(&out[b * E + tid * 4 + i], accs[tid * 4 + i]);
}

// ---------------- finalize: (acc/L)*gamma+beta ; colsum scale ---------------
__global__ void finalize_kernel(float* __restrict__ out,
                                const float* __restrict__ colsum,
                                const float* __restrict__ gamma,
                                const float* __restrict__ beta)
{
    int i = blockIdx.x * blockDim.x + threadIdx.x;
    if (i < B * E) {
        int e = i & (E - 1);
        out[i] = out[i] * (1.f / L) * gamma[e] + beta[e];
    } else if (i < B * E + B * L) {
        int j = i - B * E;
        out[i] = colsum[j] * (1.f / ((float)H * (float)L));
    }
}

// ---------------- launch ----------------------------------------------------
extern "C" void kernel_launch(void* const* d_in, const int* in_sizes, int n_in,
                              void* d_out, int out_size)
{
    const float* x      = (const float*)d_in[0];
    const float* w_qkv  = (const float*)d_in[1];
    const float* b_qkv  = (const float*)d_in[2];
    const float* w_out  = (const float*)d_in[3];
    const float* b_out  = (const float*)d_in[4];
    const float* gamma  = (const float*)d_in[5];
    const float* beta   = (const float*)d_in[6];
    float* out = (float*)d_out;

    float *hbuf, *rowsum, *colsum;
    cudaGetSymbolAddress((void**)&hbuf,   g_h);
    cudaGetSymbolAddress((void**)&rowsum, g_rowsum);
    cudaGetSymbolAddress((void**)&colsum, g_colsum);

    __nv_bfloat16 *xh, *xl, *wqh, *wql, *ch, *cl, *woh, *wol;
    __nv_bfloat16 *qhh, *qll, *khh, *vhh, *vll;
    cudaGetSymbolAddress((void**)&xh,  g_xh);
    cudaGetSymbolAddress((void**)&xl,  g_xl);
    cudaGetSymbolAddress((void**)&wqh, g_wqh);
    cudaGetSymbolAddress((void**)&wql, g_wql);
    cudaGetSymbolAddress((void**)&ch,  g_ch);
    cudaGetSymbolAddress((void**)&cl,  g_cl);
    cudaGetSymbolAddress((void**)&woh, g_woh);
    cudaGetSymbolAddress((void**)&wol, g_wol);
    cudaGetSymbolAddress((void**)&qhh, g_qhh);
    cudaGetSymbolAddress((void**)&qll, g_qll);
    cudaGetSymbolAddress((void**)&khh, g_khh);
    cudaGetSymbolAddress((void**)&vhh, g_vhh);
    cudaGetSymbolAddress((void**)&vll, g_vll);

    cudaFuncSetAttribute(gemm_qkv,
                         cudaFuncAttributeMaxDynamicSharedMemorySize, SMEM_GEMM_BYTES);
    cudaFuncSetAttribute(gemm_mma_res,
                         cudaFuncAttributeMaxDynamicSharedMemorySize, SMEM_GEMM_BYTES);
    cudaFuncSetAttribute(attn_main,
                         cudaFuncAttributeMaxDynamicSharedMemorySize, SMEM_MAIN);
    cudaFuncSetAttribute(attn_colsum,
                         cudaFuncAttributeMaxDynamicSharedMemorySize, SMEM_COLS);

    zero_kernel<<<(B * E + 255) / 256, 256>>>(out, colsum);

    // all three input splits in one launch
    const int n4tot = N4_X + N4_WQ + N4_WO;
    split_all<<<(n4tot + 255) / 256, 256>>>(
        (const float4*)x, (__nv_bfloat162*)xh, (__nv_bfloat162*)xl,
        (const float4*)w_qkv, (__nv_bfloat162*)wqh, (__nv_bfloat162*)wql,
        (const float4*)w_out, (__nv_bfloat162*)woh, (__nv_bfloat162*)wol);

    // GEMM 1 fused: qkv projection -> per-head q/k/v bf16 splits directly
    gemm_qkv<<<dim3(QKVW / 128, NTOK / 128), 256, SMEM_GEMM_BYTES>>>(
        xh, xl, wqh, wql, b_qkv, qhh, qll, khh, vhh, vll);

    // attention: single-pass ctx+rowsum, then colsum
    attn_main<<<dim3(L / 128, H, B), 256, SMEM_MAIN>>>(
        qhh, qll, khh, vhh, vll, rowsum, ch, cl);
    attn_colsum<<<dim3(L / 128, H, B), 256, SMEM_COLS>>>(
        qhh, khh, rowsum, colsum);

    // GEMM 2: h = x + ctx @ w_out^T + b_out
    gemm_mma_res<<<dim3(E / 128, NTOK / 128), 256, SMEM_GEMM_BYTES>>>(
        ch, cl, woh, wol, b_out, x, hbuf, E);

    // fused LayerNorm + pool, then finalize
    ln_pool<<<dim3(L / 64, B), 256>>>(hbuf, out);
    finalize_kernel<<<(B * E + B * L + 255) / 256, 256>>>(out, colsum, gamma, beta);
}

// round 17
// speedup vs baseline: 3.0372x; 1.0086x over previous
#include <cuda_runtime.h>
#include <cuda_bf16.h>
#include <stdint.h>
#include <math.h>

// Problem constants
#define B 8
#define L 1024
#define E 1024
#define H 16
#define D 64
#define NTOK (B * L)          // 8192
#define QKVW (3 * E)          // 3072
#define QSCALE (0.125f * 1.4426950408889634f)  // fold log2(e): exp -> exp2
#define EPS 1e-5f

// ---------------- scratch (device globals; no allocation allowed) ----------
__device__ float g_h[NTOK * E];
__device__ float g_rowsum[B * H * L];
__device__ float g_colsum[B * L];
__device__ __nv_bfloat16 g_xh[NTOK * E];
__device__ __nv_bfloat16 g_xl[NTOK * E];
__device__ __nv_bfloat16 g_wqh[QKVW * E];
__device__ __nv_bfloat16 g_wql[QKVW * E];
__device__ __nv_bfloat16 g_ch[NTOK * E];
__device__ __nv_bfloat16 g_cl[NTOK * E];
__device__ __nv_bfloat16 g_woh[E * E];
__device__ __nv_bfloat16 g_wol[E * E];
__device__ __nv_bfloat16 g_qhh[B * H * L * D];  // [bh][l][d], pre-scaled (log2 domain)
__device__ __nv_bfloat16 g_qll[B * H * L * D];
__device__ __nv_bfloat16 g_khh[B * H * L * D];  // [bh][l][d] (hi only)
__device__ __nv_bfloat16 g_vhh[B * H * D * L];  // [bh][d][l]
__device__ __nv_bfloat16 g_vll[B * H * D * L];

// ================= base-ISA PTX helpers =====================================
__device__ __forceinline__ uint32_t smem_u32(const void* p) {
    uint32_t a;
    asm("{ .reg .u64 t; cvta.to.shared.u64 t, %1; cvt.u32.u64 %0, t; }"
        : "=r"(a) : "l"(p));
    return a;
}
__device__ __forceinline__ void ldsm_x4(uint32_t addr, uint32_t& r0, uint32_t& r1,
                                        uint32_t& r2, uint32_t& r3) {
    asm volatile("ldmatrix.sync.aligned.m8n8.x4.shared.b16 {%0,%1,%2,%3}, [%4];"
                 : "=r"(r0), "=r"(r1), "=r"(r2), "=r"(r3) : "r"(addr));
}
__device__ __forceinline__ void mma16816(float* c,
                                         uint32_t a0, uint32_t a1, uint32_t a2, uint32_t a3,
                                         uint32_t b0, uint32_t b1) {
    asm volatile(
        "mma.sync.aligned.m16n8k16.row.col.f32.bf16.bf16.f32 "
        "{%0,%1,%2,%3}, {%4,%5,%6,%7}, {%8,%9}, {%0,%1,%2,%3};"
        : "+f"(c[0]), "+f"(c[1]), "+f"(c[2]), "+f"(c[3])
        : "r"(a0), "r"(a1), "r"(a2), "r"(a3), "r"(b0), "r"(b1));
}
__device__ __forceinline__ void cp16(uint32_t sdst, const void* gsrc) {
    asm volatile("cp.async.cg.shared.global [%0], [%1], 16;"
                 :: "r"(sdst), "l"(gsrc) : "memory");
}

// 2^x via MUFU (ex2.approx, ~2 ulp): 1 instruction -> relieves issue pressure
__device__ __forceinline__ float fexp2(float t) {
    float r;
    asm("ex2.approx.f32 %0, %1;" : "=f"(r) : "f"(t));
    return r;
}

__device__ __forceinline__ void splitpack(float x, float y, uint32_t& h2, uint32_t& l2) {
    __nv_bfloat16 hx = __float2bfloat16_rn(x), hy = __float2bfloat16_rn(y);
    __nv_bfloat162 hh = __halves2bfloat162(hx, hy);
    __nv_bfloat162 ll = __halves2bfloat162(
        __float2bfloat16_rn(x - __bfloat162float(hx)),
        __float2bfloat16_rn(y - __bfloat162float(hy)));
    h2 = *(uint32_t*)&hh;
    l2 = *(uint32_t*)&ll;
}

// ============ GEMM mainloop (shared): 128x128 CTA, K=32 chunks, 3 stages ===
#define GM_STAGE 32768u
#define SMEM_GEMM_BYTES (1024 + 3 * 32768)

#define GEMM_MAINLOOP()                                                        \
    float acc[2][8][4];                                                        \
    _Pragma("unroll")                                                          \
    for (int i = 0; i < 2; i++)                                                \
        _Pragma("unroll")                                                      \
        for (int j = 0; j < 8; j++)                                            \
            _Pragma("unroll")                                                  \
            for (int k = 0; k < 4; k++) acc[i][j][k] = 0.f;                    \
    const int NCHUNK = 32;                                                     \
    ISSUE_CHUNK(0, 0);                                                         \
    ISSUE_CHUNK(1, 1);                                                         \
    int buf = 0;                                                               \
    for (int c = 0; c < NCHUNK; c++) {                                         \
        if (c < NCHUNK - 1)                                                    \
            asm volatile("cp.async.wait_group 1;" ::: "memory");               \
        else                                                                   \
            asm volatile("cp.async.wait_group 0;" ::: "memory");               \
        __syncthreads();                                                       \
        if (c + 2 < NCHUNK) {                                                  \
            const int nbuf = (buf + 2 >= 3) ? buf - 1 : buf + 2;               \
            ISSUE_CHUNK(c + 2, nbuf);                                          \
        }                                                                      \
        const uint32_t Ab = s0 + (uint32_t)buf * GM_STAGE;                     \
        const uint32_t Wb = Ab + 16384u;                                       \
        _Pragma("unroll")                                                      \
        for (int ks = 0; ks < 2; ks++) {                                       \
            uint32_t aH[2][4], aL[2][4];                                       \
            _Pragma("unroll")                                                  \
            for (int mi = 0; mi < 2; mi++) {                                   \
                const int r = wm + mi * 16 + (lane & 15);                      \
                const int chunk = ks * 2 + (lane >> 4);                        \
                const uint32_t ad = Ab + (uint32_t)(r * 128)                   \
                                  + (uint32_t)(((chunk ^ (r & 7)) * 16));      \
                const uint32_t al = Ab + (uint32_t)(r * 128)                   \
                                  + (uint32_t)((((chunk + 4) ^ (r & 7)) * 16));\
                ldsm_x4(ad, aH[mi][0], aH[mi][1], aH[mi][2], aH[mi][3]);       \
                ldsm_x4(al, aL[mi][0], aL[mi][1], aL[mi][2], aL[mi][3]);       \
            }                                                                  \
            _Pragma("unroll")                                                  \
            for (int nj = 0; nj < 4; nj++) {                                   \
                const int nr = wn + nj * 16 + ((lane >> 4) & 1) * 8 + (lane & 7);\
                const int ch = ks * 2 + ((lane >> 3) & 1);                     \
                const uint32_t wd = Wb + (uint32_t)(nr * 128)                  \
                                  + (uint32_t)(((ch ^ (nr & 7)) * 16));        \
                const uint32_t wl = Wb + (uint32_t)(nr * 128)                  \
                                  + (uint32_t)((((ch + 4) ^ (nr & 7)) * 16));  \
                uint32_t w0, w1, w2, w3, v0, v1, v2, v3;                       \
                ldsm_x4(wd, w0, w1, w2, w3);                                   \
                ldsm_x4(wl, v0, v1, v2, v3);                                   \
                _Pragma("unroll")                                              \
                for (int mi = 0; mi < 2; mi++) {                               \
                    float* c0 = acc[mi][nj * 2 + 0];                           \
                    float* c1 = acc[mi][nj * 2 + 1];                           \
                    mma16816(c0, aH[mi][0], aH[mi][1], aH[mi][2], aH[mi][3], w0, w1);\
                    mma16816(c1, aH[mi][0], aH[mi][1], aH[mi][2], aH[mi][3], w2, w3);\
                    mma16816(c0, aH[mi][0], aH[mi][1], aH[mi][2], aH[mi][3], v0, v1);\
                    mma16816(c1, aH[mi][0], aH[mi][1], aH[mi][2], aH[mi][3], v2, v3);\
                    mma16816(c0, aL[mi][0], aL[mi][1], aL[mi][2], aL[mi][3], w0, w1);\
                    mma16816(c1, aL[mi][0], aL[mi][1], aL[mi][2], aL[mi][3], w2, w3);\
                }                                                              \
            }                                                                  \
        }                                                                      \
        buf = (buf + 1 >= 3) ? 0 : buf + 1;                                    \
    }

#define ISSUE_CHUNK(c, buf) do {                                              \
    const int k0_ = (c) * 32;                                                 \
    const char* gah_ = (const char*)(Ah + growA + k0_);                       \
    const char* gal_ = (const char*)(Al + growA + k0_);                       \
    const char* gwh_ = (const char*)(Wh + growW + k0_);                       \
    const char* gwl_ = (const char*)(Wl + growW + k0_);                       \
    const uint32_t st_ = s0 + (uint32_t)(buf) * GM_STAGE;                     \
    const uint32_t da_ = st_ + (uint32_t)lrow * 128u;                         \
    const uint32_t dw_ = st_ + 16384u + (uint32_t)lrow * 128u;                \
    _Pragma("unroll")                                                         \
    for (int i = 0; i < 2; i++) {                                             \
        const int cc = lhalf * 2 + i;                                         \
        const uint32_t swh = (uint32_t)((cc ^ rsw) * 16);                     \
        const uint32_t swl = (uint32_t)(((cc + 4) ^ rsw) * 16);               \
        cp16(da_ + swh, gah_ + i * 16);                                       \
        cp16(da_ + swl, gal_ + i * 16);                                       \
        cp16(dw_ + swh, gwh_ + i * 16);                                       \
        cp16(dw_ + swl, gwl_ + i * 16);                                       \
    }                                                                         \
    asm volatile("cp.async.commit_group;" ::: "memory");                      \
} while (0)

// ---- GEMM 2: h = x + ctx @ w_out^T + b_out (fp32 out) ---------------------
__global__ __launch_bounds__(256, 2) void gemm_mma_res(
    const __nv_bfloat16* __restrict__ Ah, const __nv_bfloat16* __restrict__ Al,
    const __nv_bfloat16* __restrict__ Wh, const __nv_bfloat16* __restrict__ Wl,
    const float* __restrict__ bias, const float* __restrict__ Res,
    float* __restrict__ C, int N)
{
    extern __shared__ char smraw[];
    const uint32_t sb = smem_u32(smraw);
    const uint32_t s0 = (sb + 1023) & ~1023u;

    const int tid = threadIdx.x;
    const int lane = tid & 31;
    const int wid = tid >> 5;
    const int bm = blockIdx.y * 128;
    const int bn = blockIdx.x * 128;
    const int wm = ((wid >> 1) & 3) * 32;
    const int wn = (wid & 1) * 64;

    const int lrow = tid >> 1;
    const int lhalf = tid & 1;
    const size_t growA = (size_t)(bm + lrow) * E + lhalf * 16;
    const size_t growW = (size_t)(bn + lrow) * E + lhalf * 16;
    const int rsw = lrow & 7;

    GEMM_MAINLOOP()

    const int gid = lane >> 2, qid = lane & 3;
#pragma unroll
    for (int mi = 0; mi < 2; mi++) {
        const int r = bm + wm + mi * 16 + gid;
#pragma unroll
        for (int nj = 0; nj < 8; nj++) {
            const int col = bn + wn + nj * 8 + qid * 2;
            const float2 bv = *(const float2*)(bias + col);
            const float2 r0 = *(const float2*)(Res + (size_t)r * N + col);
            const float2 r1 = *(const float2*)(Res + (size_t)(r + 8) * N + col);
            float2 o0 = {acc[mi][nj][0] + bv.x + r0.x, acc[mi][nj][1] + bv.y + r0.y};
            float2 o1 = {acc[mi][nj][2] + bv.x + r1.x, acc[mi][nj][3] + bv.y + r1.y};
            *(float2*)(C + (size_t)r * N + col) = o0;
            *(float2*)(C + (size_t)(r + 8) * N + col) = o1;
        }
    }
}

// ---- GEMM 1: qkv projection, fused epilogue -> per-head bf16 splits -------
__global__ __launch_bounds__(256, 2) void gemm_qkv(
    const __nv_bfloat16* __restrict__ Ah, const __nv_bfloat16* __restrict__ Al,
    const __nv_bfloat16* __restrict__ Wh, const __nv_bfloat16* __restrict__ Wl,
    const float* __restrict__ bias,
    __nv_bfloat16* __restrict__ qh, __nv_bfloat16* __restrict__ ql,
    __nv_bfloat16* __restrict__ kh,
    __nv_bfloat16* __restrict__ vh, __nv_bfloat16* __restrict__ vl)
{
    extern __shared__ char smraw[];
    const uint32_t sb = smem_u32(smraw);
    const uint32_t s0 = (sb + 1023) & ~1023u;

    const int tid = threadIdx.x;
    const int lane = tid & 31;
    const int wid = tid >> 5;
    const int bm = blockIdx.y * 128;
    const int bn = blockIdx.x * 128;
    const int wm = ((wid >> 1) & 3) * 32;
    const int wn = (wid & 1) * 64;

    const int lrow = tid >> 1;
    const int lhalf = tid & 1;
    const size_t growA = (size_t)(bm + lrow) * E + lhalf * 16;
    const size_t growW = (size_t)(bn + lrow) * E + lhalf * 16;
    const int rsw = lrow & 7;

    GEMM_MAINLOOP()

    __syncthreads();

    const int gid = lane >> 2, qid = lane & 3;
    const int btok = bm >> 10;
    const int l0 = bm & 1023;

    if (bn < 2 * E) {
        const bool isQ = (bn < E);
        const float sc = isQ ? QSCALE : 1.f;
        const int colbase = isQ ? bn : bn - E;
#pragma unroll
        for (int mi = 0; mi < 2; mi++) {
            const int tok = l0 + wm + mi * 16 + gid;
#pragma unroll
            for (int nj = 0; nj < 8; nj++) {
                const int col = colbase + wn + nj * 8 + qid * 2;
                const int head = col >> 6;
                const int d = col & 63;
                const float2 bv = *(const float2*)(bias + (bn + wn + nj * 8 + qid * 2));
                const float v0 = (acc[mi][nj][0] + bv.x) * sc;
                const float v1 = (acc[mi][nj][1] + bv.y) * sc;
                const float v2 = (acc[mi][nj][2] + bv.x) * sc;
                const float v3 = (acc[mi][nj][3] + bv.y) * sc;
                const size_t base = (((size_t)(btok * H + head)) * L + tok) * 64 + d;
                uint32_t h2, l2;
                if (isQ) {
                    splitpack(v0, v1, h2, l2);
                    *(uint32_t*)(qh + base) = h2;
                    *(uint32_t*)(ql + base) = l2;
                    splitpack(v2, v3, h2, l2);
                    *(uint32_t*)(qh + base + 8 * 64) = h2;
                    *(uint32_t*)(ql + base + 8 * 64) = l2;
                } else {
                    __nv_bfloat162 p0 = __halves2bfloat162(
                        __float2bfloat16_rn(v0), __float2bfloat16_rn(v1));
                    __nv_bfloat162 p1 = __halves2bfloat162(
                        __float2bfloat16_rn(v2), __float2bfloat16_rn(v3));
                    *(uint32_t*)(kh + base) = *(uint32_t*)&p0;
                    *(uint32_t*)(kh + base + 8 * 64) = *(uint32_t*)&p1;
                }
            }
        }
    } else {
        float* vt = (float*)(smraw + (s0 - sb));   // 128 x 65 fp32
        const int colbase = bn - 2 * E;
#pragma unroll
        for (int half = 0; half < 2; half++) {
            if ((wid & 1) == half) {
#pragma unroll
                for (int mi = 0; mi < 2; mi++) {
                    const int rl = wm + mi * 16 + gid;
#pragma unroll
                    for (int nj = 0; nj < 8; nj++) {
                        const int cl = nj * 8 + qid * 2;
                        const float2 bv = *(const float2*)(
                            bias + 2 * E + colbase + half * 64 + cl);
                        vt[rl * 65 + cl] = acc[mi][nj][0] + bv.x;
                        vt[rl * 65 + cl + 1] = acc[mi][nj][1] + bv.y;
                        vt[(rl + 8) * 65 + cl] = acc[mi][nj][2] + bv.x;
                        vt[(rl + 8) * 65 + cl + 1] = acc[mi][nj][3] + bv.y;
                    }
                }
            }
            __syncthreads();
            {
                const int d = tid >> 2;
                const int t0 = (tid & 3) * 32;
                const int head = (colbase >> 6) + half;
                const size_t vb = ((size_t)(btok * H + head) * D + d) * L + l0 + t0;
                uint32_t hb[16], lb[16];
#pragma unroll
                for (int i = 0; i < 16; i++)
                    splitpack(vt[(t0 + 2 * i) * 65 + d],
                              vt[(t0 + 2 * i + 1) * 65 + d], hb[i], lb[i]);
#pragma unroll
                for (int u = 0; u < 4; u++) {
                    *(uint4*)(vh + vb + u * 8) = *(uint4*)&hb[u * 4];
                    *(uint4*)(vl + vb + u * 8) = *(uint4*)&lb[u * 4];
                }
            }
            __syncthreads();
        }
    }
}
#undef ISSUE_CHUNK
#undef GEMM_MAINLOOP

// ---------------- merged exact fp32 -> bf16 hi/lo splits (x, w_qkv, w_out) --
#define N4_X   (NTOK * E / 4)
#define N4_WQ  (QKVW * E / 4)
#define N4_WO  (E * E / 4)
__global__ __launch_bounds__(256) void split_all(
    const float4* __restrict__ x, __nv_bfloat162* __restrict__ xh,
    __nv_bfloat162* __restrict__ xl,
    const float4* __restrict__ wq, __nv_bfloat162* __restrict__ wqh,
    __nv_bfloat162* __restrict__ wql,
    const float4* __restrict__ wo, __nv_bfloat162* __restrict__ woh,
    __nv_bfloat162* __restrict__ wol)
{
    int i = blockIdx.x * blockDim.x + threadIdx.x;
    const float4* src;
    __nv_bfloat162 *hi, *lo;
    int j;
    if (i < N4_X) { src = x; hi = xh; lo = xl; j = i; }
    else if (i < N4_X + N4_WQ) { src = wq; hi = wqh; lo = wql; j = i - N4_X; }
    else if (i < N4_X + N4_WQ + N4_WO) { src = wo; hi = woh; lo = wol; j = i - N4_X - N4_WQ; }
    else return;
    float4 v = src[j];
    uint32_t h0, l0, h1, l1;
    splitpack(v.x, v.y, h0, l0);
    splitpack(v.z, v.w, h1, l1);
    ((uint32_t*)hi)[j * 2 + 0] = h0;
    ((uint32_t*)hi)[j * 2 + 1] = h1;
    ((uint32_t*)lo)[j * 2 + 0] = l0;
    ((uint32_t*)lo)[j * 2 + 1] = l1;
}

// ======================= attention (m=0 softmax, single-pass ctx) ===========
#define LOAD_KH(kt, buf, STG, OFF)                                            \
    do {                                                                      \
        const int r_ = tid >> 2;                                              \
        const int q_ = tid & 3;                                               \
        const __nv_bfloat16* gh_ = kh + ((size_t)bh * L + (kt) * 64 + r_) * 64 + q_ * 16; \
        const uint32_t sh_ = s0 + (uint32_t)(buf) * (STG) + (OFF) + (uint32_t)(r_ * 128); \
        _Pragma("unroll")                                                     \
        for (int i = 0; i < 2; i++) {                                         \
            const int cc = q_ * 2 + i;                                        \
            const uint32_t sw = (uint32_t)((cc ^ (r_ & 7)) * 16);             \
            cp16(sh_ + sw, gh_ + i * 8);                                      \
        }                                                                     \
    } while (0)

// ---- attn_main: unnormalized ctx + rowsum in ONE pass ----------------------
#define PB_STAGE 24576u
#define SMEM_MAIN (1024 + 3 * 24576)
__global__ __launch_bounds__(256, 2) void attn_main(
    const __nv_bfloat16* __restrict__ qh, const __nv_bfloat16* __restrict__ ql,
    const __nv_bfloat16* __restrict__ kh,
    const __nv_bfloat16* __restrict__ vh, const __nv_bfloat16* __restrict__ vl,
    float* __restrict__ rowsum,
    __nv_bfloat16* __restrict__ ch, __nv_bfloat16* __restrict__ cl)
{
    extern __shared__ char smraw[];
    const uint32_t sb = smem_u32(smraw);
    const uint32_t s0 = (sb + 1023) & ~1023u;

    const int tid = threadIdx.x;
    const int lane = tid & 31;
    const int wid = tid >> 5;
    const int gid = lane >> 2, qid = lane & 3;
    const int bh = blockIdx.z * H + blockIdx.y;
    const int qrow0 = blockIdx.x * 128 + wid * 16;

    uint32_t aH[4][4], aL[4][4];
    {
        const size_t qb = (size_t)bh * L + qrow0;
#pragma unroll
        for (int ks = 0; ks < 4; ks++)
#pragma unroll
            for (int r = 0; r < 4; r++) {
                const int row = gid + (r & 1) * 8;
                const int col = ks * 16 + (r >> 1) * 8 + qid * 2;
                aH[ks][r] = *(const uint32_t*)(qh + (qb + row) * 64 + col);
                aL[ks][r] = *(const uint32_t*)(ql + (qb + row) * 64 + col);
            }
    }

    float lsum0 = 0.f, lsum1 = 0.f;
    float o[8][4];
#pragma unroll
    for (int j = 0; j < 8; j++)
#pragma unroll
        for (int k = 0; k < 4; k++) o[j][k] = 0.f;

#define LOAD_V(kt, buf)                                                       \
    do {                                                                      \
        const int r_ = tid >> 2;                                              \
        const int q_ = tid & 3;                                               \
        const __nv_bfloat16* gh_ = vh + ((size_t)bh * D + r_) * L + (kt) * 64 + q_ * 16; \
        const __nv_bfloat16* gl_ = vl + ((size_t)bh * D + r_) * L + (kt) * 64 + q_ * 16; \
        const uint32_t sv_ = s0 + (uint32_t)(buf) * PB_STAGE + 8192u          \
                           + (uint32_t)(r_ * 128);                            \
        _Pragma("unroll")                                                     \
        for (int i = 0; i < 2; i++) {                                         \
            const int cc = q_ * 2 + i;                                        \
            const uint32_t sw = (uint32_t)((cc ^ (r_ & 7)) * 16);             \
            cp16(sv_ + sw, gh_ + i * 8);                                      \
            cp16(sv_ + 8192u + sw, gl_ + i * 8);                              \
        }                                                                     \
    } while (0)

    LOAD_KH(0, 0, PB_STAGE, 0u);
    LOAD_V(0, 0);
    asm volatile("cp.async.commit_group;" ::: "memory");
    LOAD_KH(1, 1, PB_STAGE, 0u);
    LOAD_V(1, 1);
    asm volatile("cp.async.commit_group;" ::: "memory");

    int buf = 0;
    for (int kt = 0; kt < 16; kt++) {
        if (kt < 15)
            asm volatile("cp.async.wait_group 1;" ::: "memory");
        else
            asm volatile("cp.async.wait_group 0;" ::: "memory");
        __syncthreads();

        if (kt + 2 < 16) {
            const int nbuf = (buf + 2 >= 3) ? buf - 1 : buf + 2;
            LOAD_KH(kt + 2, nbuf, PB_STAGE, 0u);
            LOAD_V(kt + 2, nbuf);
            asm volatile("cp.async.commit_group;" ::: "memory");
        }

        float s[8][4];
#pragma unroll
        for (int t = 0; t < 8; t++)
#pragma unroll
            for (int j = 0; j < 4; j++) s[t][j] = 0.f;

        // 2-term QK: (qh + ql) x kh
        const uint32_t Kb = s0 + (uint32_t)buf * PB_STAGE;
#pragma unroll
        for (int ks = 0; ks < 4; ks++) {
#pragma unroll
            for (int nj = 0; nj < 4; nj++) {
                const int nr = nj * 16 + ((lane >> 4) & 1) * 8 + (lane & 7);
                const int ch_ = ks * 2 + ((lane >> 3) & 1);
                const uint32_t ad = Kb + (uint32_t)(nr * 128)
                                  + (uint32_t)((ch_ ^ (nr & 7)) * 16);
                uint32_t b0, b1, b2, b3;
                ldsm_x4(ad, b0, b1, b2, b3);
                mma16816(s[nj * 2 + 0], aH[ks][0], aH[ks][1], aH[ks][2],
                         aH[ks][3], b0, b1);
                mma16816(s[nj * 2 + 1], aH[ks][0], aH[ks][1], aH[ks][2],
                         aH[ks][3], b2, b3);
                mma16816(s[nj * 2 + 0], aL[ks][0], aL[ks][1], aL[ks][2],
                         aL[ks][3], b0, b1);
                mma16816(s[nj * 2 + 1], aL[ks][0], aL[ks][1], aL[ks][2],
                         aL[ks][3], b2, b3);
            }
        }

        // unnormalized e = 2^s; accumulate rowsum
#pragma unroll
        for (int t = 0; t < 8; t++) {
            s[t][0] = fexp2(s[t][0]);
            s[t][1] = fexp2(s[t][1]);
            s[t][2] = fexp2(s[t][2]);
            s[t][3] = fexp2(s[t][3]);
            lsum0 += s[t][0] + s[t][1];
            lsum1 += s[t][2] + s[t][3];
        }

        // PV: (eH + eL) x vh + eH x vl  (unnormalized accumulation)
        const uint32_t Vb = s0 + (uint32_t)buf * PB_STAGE + 8192u;
#pragma unroll
        for (int kk = 0; kk < 4; kk++) {
            uint32_t pH[4], pL[4];
            splitpack(s[2 * kk][0], s[2 * kk][1], pH[0], pL[0]);
            splitpack(s[2 * kk][2], s[2 * kk][3], pH[1], pL[1]);
            splitpack(s[2 * kk + 1][0], s[2 * kk + 1][1], pH[2], pL[2]);
            splitpack(s[2 * kk + 1][2], s[2 * kk + 1][3], pH[3], pL[3]);
#pragma unroll
            for (int nj = 0; nj < 4; nj++) {
                const int nr = nj * 16 + ((lane >> 4) & 1) * 8 + (lane & 7);
                const int ch_ = kk * 2 + ((lane >> 3) & 1);
                const uint32_t ad = Vb + (uint32_t)(nr * 128)
                                  + (uint32_t)((ch_ ^ (nr & 7)) * 16);
                uint32_t b0, b1, b2, b3, c0, c1, c2, c3;
                ldsm_x4(ad, b0, b1, b2, b3);
                ldsm_x4(ad + 8192u, c0, c1, c2, c3);
                float* o0 = o[nj * 2 + 0];
                float* o1 = o[nj * 2 + 1];
                mma16816(o0, pH[0], pH[1], pH[2], pH[3], b0, b1);
                mma16816(o1, pH[0], pH[1], pH[2], pH[3], b2, b3);
                mma16816(o0, pH[0], pH[1], pH[2], pH[3], c0, c1);
                mma16816(o1, pH[0], pH[1], pH[2], pH[3], c2, c3);
                mma16816(o0, pL[0], pL[1], pL[2], pL[3], b0, b1);
                mma16816(o1, pL[0], pL[1], pL[2], pL[3], b2, b3);
            }
        }

        buf = (buf + 1 >= 3) ? 0 : buf + 1;
    }

    // finalize rowsum across qid lanes, write, normalize o
    lsum0 += __shfl_xor_sync(0xffffffffu, lsum0, 1);
    lsum0 += __shfl_xor_sync(0xffffffffu, lsum0, 2);
    lsum1 += __shfl_xor_sync(0xffffffffu, lsum1, 1);
    lsum1 += __shfl_xor_sync(0xffffffffu, lsum1, 2);
    const int ridx = bh * L + qrow0 + gid;
    if (qid == 0) {
        rowsum[ridx] = lsum0;
        rowsum[ridx + 8] = lsum1;
    }
    const float il0 = 1.f / lsum0, il1 = 1.f / lsum1;

    const int b = blockIdx.z, h = blockIdx.y;
    const size_t tok0 = (size_t)b * L + qrow0;
#pragma unroll
    for (int j = 0; j < 8; j++) {
        const int dcol = h * 64 + j * 8 + qid * 2;
        uint32_t h2, l2;
        splitpack(o[j][0] * il0, o[j][1] * il0, h2, l2);
        *(uint32_t*)(ch + (tok0 + gid) * E + dcol) = h2;
        *(uint32_t*)(cl + (tok0 + gid) * E + dcol) = l2;
        splitpack(o[j][2] * il1, o[j][3] * il1, h2, l2);
        *(uint32_t*)(ch + (tok0 + gid + 8) * E + dcol) = h2;
        *(uint32_t*)(cl + (tok0 + gid + 8) * E + dcol) = l2;
    }
}
#undef LOAD_V

// ---- attn_colsum: avg_attn column sums (1-term QK, uses rowsum) ------------
#define SMEM_COLS (1024 + 3 * 8192 + 4096)
__global__ __launch_bounds__(256, 3) void attn_colsum(
    const __nv_bfloat16* __restrict__ qh,
    const __nv_bfloat16* __restrict__ kh,
    const float* __restrict__ rowsum,
    float* __restrict__ colsum)
{
    extern __shared__ char smraw[];
    const uint32_t sb = smem_u32(smraw);
    const uint32_t s0 = (sb + 1023) & ~1023u;
    float* colAll = (float*)(smraw + (s0 - sb) + 3 * 8192);

    const int tid = threadIdx.x;
    const int lane = tid & 31;
    const int wid = tid >> 5;
    const int gid = lane >> 2, qid = lane & 3;
    const int bh = blockIdx.z * H + blockIdx.y;
    const int qrow0 = blockIdx.x * 128 + wid * 16;

#pragma unroll
    for (int i = 0; i < 4; i++) colAll[tid * 4 + i] = 0.f;

    uint32_t aH[4][4];
    {
        const size_t qb = (size_t)bh * L + qrow0;
#pragma unroll
        for (int ks = 0; ks < 4; ks++)
#pragma unroll
            for (int r = 0; r < 4; r++) {
                const int row = gid + (r & 1) * 8;
                const int col = ks * 16 + (r >> 1) * 8 + qid * 2;
                aH[ks][r] = *(const uint32_t*)(qh + (qb + row) * 64 + col);
            }
    }

    const int ridx = bh * L + qrow0 + gid;
    const float il0 = 1.f / rowsum[ridx], il1 = 1.f / rowsum[ridx + 8];

    LOAD_KH(0, 0, 8192u, 0u);
    asm volatile("cp.async.commit_group;" ::: "memory");
    LOAD_KH(1, 1, 8192u, 0u);
    asm volatile("cp.async.commit_group;" ::: "memory");

    int buf = 0;
    for (int kt = 0; kt < 16; kt++) {
        if (kt < 15)
            asm volatile("cp.async.wait_group 1;" ::: "memory");
        else
            asm volatile("cp.async.wait_group 0;" ::: "memory");
        __syncthreads();

        if (kt + 2 < 16) {
            const int nbuf = (buf + 2 >= 3) ? buf - 1 : buf + 2;
            LOAD_KH(kt + 2, nbuf, 8192u, 0u);
            asm volatile("cp.async.commit_group;" ::: "memory");
        }

        float s[8][4];
#pragma unroll
        for (int t = 0; t < 8; t++)
#pragma unroll
            for (int j = 0; j < 4; j++) s[t][j] = 0.f;

        const uint32_t Kb = s0 + (uint32_t)buf * 8192u;
#pragma unroll
        for (int ks = 0; ks < 4; ks++) {
#pragma unroll
            for (int nj = 0; nj < 4; nj++) {
                const int nr = nj * 16 + ((lane >> 4) & 1) * 8 + (lane & 7);
                const int ch = ks * 2 + ((lane >> 3) & 1);
                const uint32_t ad = Kb + (uint32_t)(nr * 128)
                                  + (uint32_t)((ch ^ (nr & 7)) * 16);
                uint32_t b0, b1, b2, b3;
                ldsm_x4(ad, b0, b1, b2, b3);
                mma16816(s[nj * 2 + 0], aH[ks][0], aH[ks][1], aH[ks][2],
                         aH[ks][3], b0, b1);
                mma16816(s[nj * 2 + 1], aH[ks][0], aH[ks][1], aH[ks][2],
                         aH[ks][3], b2, b3);
            }
        }

#pragma unroll
        for (int t = 0; t < 8; t++) {
            float v0 = fexp2(s[t][0]) * il0 + fexp2(s[t][2]) * il1;
            float v1 = fexp2(s[t][1]) * il0 + fexp2(s[t][3]) * il1;
            v0 += __shfl_xor_sync(0xffffffffu, v0, 4);
            v0 += __shfl_xor_sync(0xffffffffu, v0, 8);
            v0 += __shfl_xor_sync(0xffffffffu, v0, 16);
            v1 += __shfl_xor_sync(0xffffffffu, v1, 4);
            v1 += __shfl_xor_sync(0xffffffffu, v1, 8);
            v1 += __shfl_xor_sync(0xffffffffu, v1, 16);
            if (gid == 0) {
                const int col = kt * 64 + t * 8 + qid * 2;
                atomicAdd(&colAll[col], v0);
                atomicAdd(&colAll[col + 1], v1);
            }
        }

        buf = (buf + 1 >= 3) ? 0 : buf + 1;
    }

    __syncthreads();
    const int b = blockIdx.z;
#pragma unroll
    for (int i = 0; i < 4; i++)
        atomicAdd(&colsum[b * L + tid * 4 + i], colAll[tid * 4 + i]);
}
#undef LOAD_KH

// ---------------- zero init -------------------------------------------------
__global__ void zero_kernel(float* __restrict__ out, float* __restrict__ colsum) {
    int i = blockIdx.x * blockDim.x + threadIdx.x;
    if (i < B * E) { out[i] = 0.f; colsum[i] = 0.f; }
}

// ---------------- fused LayerNorm + pool ------------------------------------
__global__ __launch_bounds__(256) void ln_pool(
    const float* __restrict__ hbuf, float* __restrict__ out)
{
    __shared__ float accs[1024];
    const int tid = threadIdx.x;
    const int lane = tid & 31, wid = tid >> 5;
    const int b = blockIdx.y;
    const int l0 = blockIdx.x * 64;

#pragma unroll
    for (int i = 0; i < 4; i++) accs[tid * 4 + i] = 0.f;
    __syncthreads();

    float a[8][4];
#pragma unroll
    for (int i = 0; i < 8; i++)
#pragma unroll
        for (int j = 0; j < 4; j++) a[i][j] = 0.f;

    for (int r = 0; r < 8; r++) {
        const size_t row = (size_t)(b * L + l0 + wid * 8 + r);
        float4 v[8];
        float s = 0.f, s2 = 0.f;
#pragma unroll
        for (int i = 0; i < 8; i++) {
            v[i] = *(const float4*)(hbuf + row * E + i * 128 + lane * 4);
            s += v[i].x + v[i].y + v[i].z + v[i].w;
            s2 += v[i].x * v[i].x + v[i].y * v[i].y + v[i].z * v[i].z + v[i].w * v[i].w;
        }
#pragma unroll
        for (int off = 16; off >= 1; off >>= 1) {
            s += __shfl_xor_sync(0xffffffffu, s, off);
            s2 += __shfl_xor_sync(0xffffffffu, s2, off);
        }
        const float mu = s * (1.f / E);
        const float rstd = rsqrtf(s2 * (1.f / E) - mu * mu + EPS);
        const float nm = mu * rstd;
#pragma unroll
        for (int i = 0; i < 8; i++) {
            a[i][0] = fmaf(v[i].x, rstd, a[i][0] - nm);
            a[i][1] = fmaf(v[i].y, rstd, a[i][1] - nm);
            a[i][2] = fmaf(v[i].z, rstd, a[i][2] - nm);
            a[i][3] = fmaf(v[i].w, rstd, a[i][3] - nm);
        }
    }

#pragma unroll
    for (int i = 0; i < 8; i++) {
        const int e = i * 128 + lane * 4;
        atomicAdd(&accs[e + 0], a[i][0]);
        atomicAdd(&accs[e + 1], a[i][1]);
        atomicAdd(&accs[e + 2], a[i][2]);
        atomicAdd(&accs[e + 3], a[i][3]);
    }
    __syncthreads();
#pragma unroll
    for (int i = 0; i < 4; i++)
        atomicAdd(&out[b * E + tid * 4 + i], accs[tid * 4 + i]);
}

// ---------------- finalize: (acc/L)*gamma+beta ; colsum scale ---------------
__global__ void finalize_kernel(float* __restrict__ out,
                                const float* __restrict__ colsum,
                                const float* __restrict__ gamma,
                                const float* __restrict__ beta)
{
    int i = blockIdx.x * blockDim.x + threadIdx.x;
    if (i < B * E) {
        int e = i & (E - 1);
        out[i] = out[i] * (1.f / L) * gamma[e] + beta[e];
    } else if (i < B * E + B * L) {
        int j = i - B * E;
        out[i] = colsum[j] * (1.f / ((float)H * (float)L));
    }
}

// ---------------- launch ----------------------------------------------------
extern "C" void kernel_launch(void* const* d_in, const int* in_sizes, int n_in,
                              void* d_out, int out_size)
{
    const float* x      = (const float*)d_in[0];
    const float* w_qkv  = (const float*)d_in[1];
    const float* b_qkv  = (const float*)d_in[2];
    const float* w_out  = (const float*)d_in[3];
    const float* b_out  = (const float*)d_in[4];
    const float* gamma  = (const float*)d_in[5];
    const float* beta   = (const float*)d_in[6];
    float* out = (float*)d_out;

    float *hbuf, *rowsum, *colsum;
    cudaGetSymbolAddress((void**)&hbuf,   g_h);
    cudaGetSymbolAddress((void**)&rowsum, g_rowsum);
    cudaGetSymbolAddress((void**)&colsum, g_colsum);

    __nv_bfloat16 *xh, *xl, *wqh, *wql, *ch, *cl, *woh, *wol;
    __nv_bfloat16 *qhh, *qll, *khh, *vhh, *vll;
    cudaGetSymbolAddress((void**)&xh,  g_xh);
    cudaGetSymbolAddress((void**)&xl,  g_xl);
    cudaGetSymbolAddress((void**)&wqh, g_wqh);
    cudaGetSymbolAddress((void**)&wql, g_wql);
    cudaGetSymbolAddress((void**)&ch,  g_ch);
    cudaGetSymbolAddress((void**)&cl,  g_cl);
    cudaGetSymbolAddress((void**)&woh, g_woh);
    cudaGetSymbolAddress((void**)&wol, g_wol);
    cudaGetSymbolAddress((void**)&qhh, g_qhh);
    cudaGetSymbolAddress((void**)&qll, g_qll);
    cudaGetSymbolAddress((void**)&khh, g_khh);
    cudaGetSymbolAddress((void**)&vhh, g_vhh);
    cudaGetSymbolAddress((void**)&vll, g_vll);

    cudaFuncSetAttribute(gemm_qkv,
                         cudaFuncAttributeMaxDynamicSharedMemorySize, SMEM_GEMM_BYTES);
    cudaFuncSetAttribute(gemm_mma_res,
                         cudaFuncAttributeMaxDynamicSharedMemorySize, SMEM_GEMM_BYTES);
    cudaFuncSetAttribute(attn_main,
                         cudaFuncAttributeMaxDynamicSharedMemorySize, SMEM_MAIN);
    cudaFuncSetAttribute(attn_colsum,
                         cudaFuncAttributeMaxDynamicSharedMemorySize, SMEM_COLS);

    zero_kernel<<<(B * E + 255) / 256, 256>>>(out, colsum);

    // all three input splits in one launch
    const int n4tot = N4_X + N4_WQ + N4_WO;
    split_all<<<(n4tot + 255) / 256, 256>>>(
        (const float4*)x, (__nv_bfloat162*)xh, (__nv_bfloat162*)xl,
        (const float4*)w_qkv, (__nv_bfloat162*)wqh, (__nv_bfloat162*)wql,
        (const float4*)w_out, (__nv_bfloat162*)woh, (__nv_bfloat162*)wol);

    // GEMM 1 fused: qkv projection -> per-head q/k/v bf16 splits directly
    gemm_qkv<<<dim3(QKVW / 128, NTOK / 128), 256, SMEM_GEMM_BYTES>>>(
        xh, xl, wqh, wql, b_qkv, qhh, qll, khh, vhh, vll);

    // attention: single-pass ctx+rowsum
    attn_main<<<dim3(L / 128, H, B), 256, SMEM_MAIN>>>(
        qhh, qll, khh, vhh, vll, rowsum, ch, cl);

    // fork: attn_colsum runs concurrently with gemm2 + ln_pool
    cudaStream_t s2;
    cudaEvent_t ev_fork, ev_join;
    cudaStreamCreateWithFlags(&s2, cudaStreamNonBlocking);
    cudaEventCreateWithFlags(&ev_fork, cudaEventDisableTiming);
    cudaEventCreateWithFlags(&ev_join, cudaEventDisableTiming);

    cudaEventRecord(ev_fork, 0);
    cudaStreamWaitEvent(s2, ev_fork, 0);
    attn_colsum<<<dim3(L / 128, H, B), 256, SMEM_COLS, s2>>>(
        qhh, khh, rowsum, colsum);
    cudaEventRecord(ev_join, s2);

    // main branch: GEMM 2 + LayerNorm/pool
    gemm_mma_res<<<dim3(E / 128, NTOK / 128), 256, SMEM_GEMM_BYTES>>>(
        ch, cl, woh, wol, b_out, x, hbuf, E);
    ln_pool<<<dim3(L / 64, B), 256>>>(hbuf, out);

    // join, then finalize
    cudaStreamWaitEvent(0, ev_join, 0);
    finalize_kernel<<<(B * E + B * L + 255) / 256, 256>>>(out, colsum, gamma, beta);

    cudaEventDestroy(ev_fork);
    cudaEventDestroy(ev_join);
    cudaStreamDestroy(s2);
}